// round 2
// baseline (speedup 1.0000x reference)
#include <cuda_runtime.h>
#include <cuda_bf16.h>

// Comparator4Bit: A,B are (N,4) float32 with values in {0,1}.
// col0 = bit3 (MSB) ... col3 = bit0 (LSB).
// out[0:N] = (valA > valB) ? 1.0f : 0.0f;  out[N:2N] = (valA == valB) ? 1.0f : 0.0f
//
// Pure HBM-bound streaming: 128 MiB read + 32 MiB write (~168 MB).
// Single-wave persistent grid (148 SMs x 6 CTAs) with a grid-stride loop:
// removes the 4.6-wave quantization tail that capped DRAM at 74%.

static __device__ __forceinline__ int pack_row(const float4 v) {
    // values are exactly 0.0f or 1.0f
    return (int(v.x) << 3) | (int(v.y) << 2) | (int(v.z) << 1) | int(v.w);
}

static __device__ __forceinline__ float4 ldcs4(const float4* p) {
    return __ldcs(p);
}

__global__ void __launch_bounds__(256, 6)
comparator4bit_kernel(const float4* __restrict__ A4,
                      const float4* __restrict__ B4,
                      float4* __restrict__ out_gt4,
                      float4* __restrict__ out_eq4,
                      int n_units)   // n_rows / 4 work units
{
    int stride = gridDim.x * blockDim.x;
    for (int t = blockIdx.x * blockDim.x + threadIdx.x; t < n_units; t += stride) {
        int base = t * 4;

        // Front-batch all 8 loads for max MLP (streaming, evict-first).
        float4 a0 = ldcs4(A4 + base + 0);
        float4 a1 = ldcs4(A4 + base + 1);
        float4 a2 = ldcs4(A4 + base + 2);
        float4 a3 = ldcs4(A4 + base + 3);
        float4 b0 = ldcs4(B4 + base + 0);
        float4 b1 = ldcs4(B4 + base + 1);
        float4 b2 = ldcs4(B4 + base + 2);
        float4 b3 = ldcs4(B4 + base + 3);

        int va0 = pack_row(a0), vb0 = pack_row(b0);
        int va1 = pack_row(a1), vb1 = pack_row(b1);
        int va2 = pack_row(a2), vb2 = pack_row(b2);
        int va3 = pack_row(a3), vb3 = pack_row(b3);

        float4 gt, eq;
        gt.x = (va0 > vb0) ? 1.0f : 0.0f;  eq.x = (va0 == vb0) ? 1.0f : 0.0f;
        gt.y = (va1 > vb1) ? 1.0f : 0.0f;  eq.y = (va1 == vb1) ? 1.0f : 0.0f;
        gt.z = (va2 > vb2) ? 1.0f : 0.0f;  eq.z = (va2 == vb2) ? 1.0f : 0.0f;
        gt.w = (va3 > vb3) ? 1.0f : 0.0f;  eq.w = (va3 == vb3) ? 1.0f : 0.0f;

        __stcs(out_gt4 + t, gt);
        __stcs(out_eq4 + t, eq);
    }
}

extern "C" void kernel_launch(void* const* d_in, const int* in_sizes, int n_in,
                              void* d_out, int out_size) {
    const float* A = (const float*)d_in[0];
    const float* B = (const float*)d_in[1];
    float* out = (float*)d_out;

    int n_rows = in_sizes[0] / 4;   // (N,4) float32 -> N rows
    int n_units = n_rows / 4;       // 4 rows per work unit

    float* out_gt = out;            // [0:N)
    float* out_eq = out + n_rows;   // [N:2N)

    const int threads = 256;
    // One wave: 148 SMs x 6 CTAs (pinned by __launch_bounds__(256, 6)).
    int blocks = 148 * 6;
    int needed = (n_units + threads - 1) / threads;
    if (blocks > needed) blocks = needed;

    comparator4bit_kernel<<<blocks, threads>>>(
        (const float4*)A, (const float4*)B,
        (float4*)out_gt, (float4*)out_eq, n_units);
}

// round 3
// speedup vs baseline: 1.0594x; 1.0594x over previous
#include <cuda_runtime.h>
#include <cuda_bf16.h>

// Comparator4Bit: A,B are (N,4) float32 with values in {0,1}.
// col0 = bit3 (MSB) ... col3 = bit0 (LSB).
// out[0:N] = (valA > valB) ? 1.0f : 0.0f;  out[N:2N] = (valA == valB) ? 1.0f : 0.0f
//
// Pure HBM-bound streaming: 128 MiB read + 32 MiB write (~168 MB).
// Flat launch (no grid-stride loop — independent CTAs hide DRAM latency better
// than loop-carried iterations, per R2 regression). 2 rows/thread keeps regs
// <= 32 so launch_bounds(256,8) reaches 8 CTAs/SM = 100% occupancy.

static __device__ __forceinline__ int pack_row(const float4 v) {
    // values are exactly 0.0f or 1.0f
    return (int(v.x) << 3) | (int(v.y) << 2) | (int(v.z) << 1) | int(v.w);
}

__global__ void __launch_bounds__(256, 8)
comparator4bit_kernel(const float4* __restrict__ A4,
                      const float4* __restrict__ B4,
                      float2* __restrict__ out_gt2,
                      float2* __restrict__ out_eq2,
                      int n_units)   // n_rows / 2 work units
{
    int t = blockIdx.x * blockDim.x + threadIdx.x;
    if (t >= n_units) return;
    int base = t * 2;

    // Front-batch all 4 loads for max MLP.
    float4 a0 = A4[base + 0];
    float4 a1 = A4[base + 1];
    float4 b0 = B4[base + 0];
    float4 b1 = B4[base + 1];

    int va0 = pack_row(a0), vb0 = pack_row(b0);
    int va1 = pack_row(a1), vb1 = pack_row(b1);

    float2 gt, eq;
    gt.x = (va0 > vb0) ? 1.0f : 0.0f;  eq.x = (va0 == vb0) ? 1.0f : 0.0f;
    gt.y = (va1 > vb1) ? 1.0f : 0.0f;  eq.y = (va1 == vb1) ? 1.0f : 0.0f;

    out_gt2[t] = gt;
    out_eq2[t] = eq;
}

extern "C" void kernel_launch(void* const* d_in, const int* in_sizes, int n_in,
                              void* d_out, int out_size) {
    const float* A = (const float*)d_in[0];
    const float* B = (const float*)d_in[1];
    float* out = (float*)d_out;

    int n_rows = in_sizes[0] / 4;   // (N,4) float32 -> N rows
    int n_units = n_rows / 2;       // 2 rows per thread

    float* out_gt = out;            // [0:N)
    float* out_eq = out + n_rows;   // [N:2N)

    const int threads = 256;
    int blocks = (n_units + threads - 1) / threads;

    comparator4bit_kernel<<<blocks, threads>>>(
        (const float4*)A, (const float4*)B,
        (float2*)out_gt, (float2*)out_eq, n_units);
}